// round 3
// baseline (speedup 1.0000x reference)
#include <cuda_runtime.h>
#include <math.h>

#define BDIM 8
#define TDIM 128
#define EDIM 30522
#define HDIM 1000
#define NZDIM 10000
#define GDIM 4000   // 4*H
#define MDIM 1024   // T*B

// ---------------- scratch (device globals; referenced ONLY from device code) ----------------
__device__ float g_Xg[(size_t)MDIM * GDIM];          // encoder input projection [T*B, 4H]
__device__ float g_enc[(size_t)TDIM * BDIM * HDIM];  // encoder outputs [T, B, H]
__device__ float g_hbuf[2][BDIM * HDIM];             // encoder double-buffered hidden
__device__ float g_c[BDIM * HDIM];                   // cell state
__device__ float g_h[BDIM * HDIM];                   // decoder hidden (current)
__device__ float g_hn[BDIM * HDIM];                  // decoder hidden (next)
__device__ float g_inp[BDIM * EDIM];                 // decoder input feedback
__device__ float g_emb[BDIM * HDIM];
__device__ float g_aw[BDIM * TDIM];
__device__ float g_app[BDIM * HDIM];
__device__ float g_outc[BDIM * HDIM];

__device__ __forceinline__ float sigm(float x) { return 1.f / (1.f + __expf(-x)); }

__device__ __forceinline__ float wredsum(float v) {
#pragma unroll
    for (int o = 16; o; o >>= 1) v += __shfl_xor_sync(0xffffffffu, v, o);
    return v;
}

// ---------------- init: zero h0, c0 ----------------
__global__ __launch_bounds__(256) void k_init() {
    int i = blockIdx.x * 256 + threadIdx.x;
    if (i < BDIM * HDIM) { g_hbuf[0][i] = 0.f; g_c[i] = 0.f; }
}

// ---------------- encoder input projection GEMM ----------------
// Xg[m][n] = bih[n] + bhh[n] + sum_k input[b][t][k] * Wih[n][k],  m = t*B+b
__global__ __launch_bounds__(256, 2) void k_enc_proj(
    const float* __restrict__ X, const float* __restrict__ W,
    const float* __restrict__ bih, const float* __restrict__ bhh) {
    __shared__ float As[16][128];
    __shared__ float Bs[16][128];
    const int K = EDIM;
    int tid = threadIdx.x;
    int bm = blockIdx.y * 128;
    int bn = blockIdx.x * 128;

    int lr = tid >> 1;              // load row 0..127
    int lh = (tid & 1) * 8;         // k half offset
    int am = bm + lr;
    int ab = am & 7, at = am >> 3;  // m = t*8 + b
    const float* Arow = X + ((size_t)ab * TDIM + at) * EDIM;
    int bj = bn + lr;
    const float* Brow = (bj < GDIM) ? (W + (size_t)bj * K) : (const float*)0;

    int tm = (tid >> 4) << 3;
    int tn = (tid & 15) << 3;
    float acc[8][8];
#pragma unroll
    for (int i = 0; i < 8; i++)
#pragma unroll
        for (int j = 0; j < 8; j++) acc[i][j] = 0.f;

    for (int k0 = 0; k0 < K; k0 += 16) {
#pragma unroll
        for (int q = 0; q < 4; q++) {
            int kk = lh + q * 2;
            int k = k0 + kk;
            float2 v = make_float2(0.f, 0.f);
            if (k + 1 < K) v = *(const float2*)(Arow + k);
            else if (k < K) v.x = Arow[k];
            As[kk][lr] = v.x; As[kk + 1][lr] = v.y;
            float2 wv = make_float2(0.f, 0.f);
            if (Brow) {
                if (k + 1 < K) wv = *(const float2*)(Brow + k);
                else if (k < K) wv.x = Brow[k];
            }
            Bs[kk][lr] = wv.x; Bs[kk + 1][lr] = wv.y;
        }
        __syncthreads();
#pragma unroll
        for (int kk = 0; kk < 16; kk++) {
            float a[8], b[8];
            *(float4*)&a[0] = *(const float4*)&As[kk][tm];
            *(float4*)&a[4] = *(const float4*)&As[kk][tm + 4];
            *(float4*)&b[0] = *(const float4*)&Bs[kk][tn];
            *(float4*)&b[4] = *(const float4*)&Bs[kk][tn + 4];
#pragma unroll
            for (int i = 0; i < 8; i++)
#pragma unroll
                for (int j = 0; j < 8; j++) acc[i][j] += a[i] * b[j];
        }
        __syncthreads();
    }
#pragma unroll
    for (int i = 0; i < 8; i++) {
        int m = bm + tm + i;
#pragma unroll
        for (int j = 0; j < 8; j++) {
            int n = bn + tn + j;
            if (n < GDIM) g_Xg[(size_t)m * GDIM + n] = acc[i][j] + bih[n] + bhh[n];
        }
    }
}

// ---------------- encoder recurrence step ----------------
__global__ __launch_bounds__(256) void k_enc_step(const float* __restrict__ Whh, int t) {
    __shared__ float hs[BDIM][HDIM];
    int tid = threadIdx.x;
    int rp = t & 1;
    const float* hin = g_hbuf[rp];
    float* hout = g_hbuf[rp ^ 1];
    for (int i = tid; i < BDIM * HDIM; i += 256) hs[i / HDIM][i % HDIM] = hin[i];
    __syncthreads();
    int w = tid >> 5, lane = tid & 31;
    int j = blockIdx.x * 8 + w;
    const float* w0 = Whh + (size_t)j * HDIM;
    const float* w1 = Whh + (size_t)(HDIM + j) * HDIM;
    const float* w2 = Whh + (size_t)(2 * HDIM + j) * HDIM;
    const float* w3 = Whh + (size_t)(3 * HDIM + j) * HDIM;
    float acc[4][8];
#pragma unroll
    for (int g = 0; g < 4; g++)
#pragma unroll
        for (int b = 0; b < 8; b++) acc[g][b] = 0.f;

    for (int k = lane * 4; k < HDIM; k += 128) {
        float4 v0 = *(const float4*)(w0 + k);
        float4 v1 = *(const float4*)(w1 + k);
        float4 v2 = *(const float4*)(w2 + k);
        float4 v3 = *(const float4*)(w3 + k);
#pragma unroll
        for (int b = 0; b < 8; b++) {
            float4 h4 = *(const float4*)&hs[b][k];
            acc[0][b] += v0.x * h4.x + v0.y * h4.y + v0.z * h4.z + v0.w * h4.w;
            acc[1][b] += v1.x * h4.x + v1.y * h4.y + v1.z * h4.z + v1.w * h4.w;
            acc[2][b] += v2.x * h4.x + v2.y * h4.y + v2.z * h4.z + v2.w * h4.w;
            acc[3][b] += v3.x * h4.x + v3.y * h4.y + v3.z * h4.z + v3.w * h4.w;
        }
    }
#pragma unroll
    for (int g = 0; g < 4; g++)
#pragma unroll
        for (int b = 0; b < 8; b++) acc[g][b] = wredsum(acc[g][b]);
    if (lane < 8) {
        int b = lane;
        const float* xr = g_Xg + ((size_t)t * BDIM + b) * GDIM;
        float gi = xr[j] + acc[0][b];
        float gf = xr[HDIM + j] + acc[1][b];
        float gg = xr[2 * HDIM + j] + acc[2][b];
        float go = xr[3 * HDIM + j] + acc[3][b];
        float cv = sigm(gf) * g_c[b * HDIM + j] + sigm(gi) * tanhf(gg);
        float hv = sigm(go) * tanhf(cv);
        g_c[b * HDIM + j] = cv;
        hout[b * HDIM + j] = hv;
        g_enc[((size_t)t * BDIM + b) * HDIM + j] = hv;
    }
}

// ---------------- prep decoder: h <- encoder final h (hbuf[0]); inp <- init_dec ----------------
__global__ __launch_bounds__(256) void k_prepdec(const float* __restrict__ init_dec) {
    int i = blockIdx.x * 256 + threadIdx.x;
    if (i < BDIM * EDIM) g_inp[i] = init_dec[i];
    if (i < BDIM * HDIM) g_h[i] = g_hbuf[0][i];
}

// ---------------- concat GEMM (mode 0: emb, mode 1: comb) ----------------
// All device-global operands resolved INSIDE device code (never passed as args).
#define KC 1024
__global__ __launch_bounds__(256) void k_cgemm(
    const float* __restrict__ ext,           // noise1 slice for mode 0; unused mode 1
    const float* __restrict__ W, const float* __restrict__ bias, int mode) {
    const float* A;  const float* Bsrc;  float* out;
    int lenA, lenB, relu;
    if (mode == 0) { A = g_inp; Bsrc = ext;   lenA = EDIM; lenB = NZDIM; out = g_emb;  relu = 0; }
    else           { A = g_emb; Bsrc = g_app; lenA = HDIM; lenB = HDIM;  out = g_outc; relu = 1; }

    __shared__ float xs[BDIM][KC];
    int K = lenA + lenB;
    int tid = threadIdx.x, w = tid >> 5, lane = tid & 31;
    int j = blockIdx.x * 8 + w;
    const float* wr = W + (size_t)j * K;
    float acc[8];
#pragma unroll
    for (int b = 0; b < 8; b++) acc[b] = 0.f;

    for (int k0 = 0; k0 < K; k0 += KC) {
        int kc = min(KC, K - k0);
        int kcp = (kc + 3) & ~3;
        __syncthreads();
        for (int i = tid; i < BDIM * kcp; i += 256) {
            int b = i / kcp, kk = i - b * kcp;
            int k = k0 + kk;
            float v = 0.f;
            if (kk < kc) v = (k < lenA) ? A[(size_t)b * lenA + k]
                                        : Bsrc[(size_t)b * lenB + (k - lenA)];
            xs[b][kk] = v;
        }
        __syncthreads();
#pragma unroll 4
        for (int kk = lane * 2; kk < kc; kk += 64) {
            int k = k0 + kk;
            float2 wv;
            if (kk + 2 <= kc) wv = *(const float2*)(wr + k);
            else { wv.x = wr[k]; wv.y = 0.f; }
#pragma unroll
            for (int b = 0; b < 8; b++) {
                float2 xv = *(const float2*)&xs[b][kk];
                acc[b] += wv.x * xv.x;
                acc[b] += wv.y * xv.y;
            }
        }
    }
#pragma unroll
    for (int b = 0; b < 8; b++) acc[b] = wredsum(acc[b]);
    if (lane < 8) {
        float v = acc[lane] + bias[j];
        if (relu) v = fmaxf(v, 0.f);
        out[lane * HDIM + j] = v;
    }
}

// ---------------- attention scores + softmax ----------------
__global__ __launch_bounds__(256) void k_attn(
    const float* __restrict__ attW, const float* __restrict__ attb,
    const float* __restrict__ n2) {
    int b = blockIdx.x;
    __shared__ float xs[3 * HDIM];
    __shared__ float sc[TDIM];
    int tid = threadIdx.x;
    for (int i = tid; i < HDIM; i += 256) {
        xs[i] = g_emb[b * HDIM + i];
        xs[HDIM + i] = g_h[b * HDIM + i];
        xs[2 * HDIM + i] = n2[b * HDIM + i];
    }
    __syncthreads();
    int w = tid >> 5, lane = tid & 31;
    for (int t = w; t < TDIM; t += 8) {
        const float* wr = attW + (size_t)t * 3 * HDIM;
        float a = 0.f;
        for (int k = lane * 4; k < 3 * HDIM; k += 128) {
            float4 wv = *(const float4*)(wr + k);
            float4 xv = *(const float4*)&xs[k];
            a += wv.x * xv.x + wv.y * xv.y + wv.z * xv.z + wv.w * xv.w;
        }
        a = wredsum(a);
        if (lane == 0) sc[t] = a + attb[t];
    }
    __syncthreads();
    if (w == 0) {
        float4 v = *(const float4*)&sc[lane * 4];
        float m = fmaxf(fmaxf(v.x, v.y), fmaxf(v.z, v.w));
#pragma unroll
        for (int o = 16; o; o >>= 1) m = fmaxf(m, __shfl_xor_sync(0xffffffffu, m, o));
        float e0 = __expf(v.x - m), e1 = __expf(v.y - m);
        float e2 = __expf(v.z - m), e3 = __expf(v.w - m);
        float s = wredsum(e0 + e1 + e2 + e3);
        float inv = 1.f / s;
        float4 r = make_float4(e0 * inv, e1 * inv, e2 * inv, e3 * inv);
        *(float4*)&g_aw[b * TDIM + lane * 4] = r;
    }
}

// ---------------- applied = aw @ enc ----------------
__global__ __launch_bounds__(256) void k_applied() {
    int b = blockIdx.x >> 2;
    int h0 = (blockIdx.x & 3) * 250;
    __shared__ float aws[TDIM];
    if (threadIdx.x < TDIM) aws[threadIdx.x] = g_aw[b * TDIM + threadIdx.x];
    __syncthreads();
    if (threadIdx.x < 250) {
        int h = h0 + threadIdx.x;
        float a = 0.f;
#pragma unroll 8
        for (int t = 0; t < TDIM; t++)
            a += aws[t] * g_enc[((size_t)t * BDIM + b) * HDIM + h];
        g_app[b * HDIM + h] = a;
    }
}

// ---------------- decoder LSTM: reads g_outc, g_h, g_c; writes g_hn, g_c ----------------
__global__ __launch_bounds__(256) void k_declstm(
    const float* __restrict__ Wih, const float* __restrict__ Whh,
    const float* __restrict__ bih, const float* __restrict__ bhh) {
    __shared__ float xs[BDIM][HDIM];
    int tid = threadIdx.x, w = tid >> 5, lane = tid & 31;
    int j = blockIdx.x * 8 + w;
    float acc[4][8];
#pragma unroll
    for (int g = 0; g < 4; g++)
#pragma unroll
        for (int b = 0; b < 8; b++) acc[g][b] = 0.f;

    for (int src = 0; src < 2; src++) {
        const float* s = src ? (const float*)g_h : (const float*)g_outc;
        const float* Wm = src ? Whh : Wih;
        __syncthreads();
        for (int i = tid; i < BDIM * HDIM; i += 256) xs[i / HDIM][i % HDIM] = s[i];
        __syncthreads();
        const float* w0 = Wm + (size_t)j * HDIM;
        const float* w1 = Wm + (size_t)(HDIM + j) * HDIM;
        const float* w2 = Wm + (size_t)(2 * HDIM + j) * HDIM;
        const float* w3 = Wm + (size_t)(3 * HDIM + j) * HDIM;
        for (int k = lane * 4; k < HDIM; k += 128) {
            float4 v0 = *(const float4*)(w0 + k);
            float4 v1 = *(const float4*)(w1 + k);
            float4 v2 = *(const float4*)(w2 + k);
            float4 v3 = *(const float4*)(w3 + k);
#pragma unroll
            for (int b = 0; b < 8; b++) {
                float4 h4 = *(const float4*)&xs[b][k];
                acc[0][b] += v0.x * h4.x + v0.y * h4.y + v0.z * h4.z + v0.w * h4.w;
                acc[1][b] += v1.x * h4.x + v1.y * h4.y + v1.z * h4.z + v1.w * h4.w;
                acc[2][b] += v2.x * h4.x + v2.y * h4.y + v2.z * h4.z + v2.w * h4.w;
                acc[3][b] += v3.x * h4.x + v3.y * h4.y + v3.z * h4.z + v3.w * h4.w;
            }
        }
    }
#pragma unroll
    for (int g = 0; g < 4; g++)
#pragma unroll
        for (int b = 0; b < 8; b++) acc[g][b] = wredsum(acc[g][b]);
    if (lane < 8) {
        int b = lane;
        float gi = acc[0][b] + bih[j] + bhh[j];
        float gf = acc[1][b] + bih[HDIM + j] + bhh[HDIM + j];
        float gg = acc[2][b] + bih[2 * HDIM + j] + bhh[2 * HDIM + j];
        float go = acc[3][b] + bih[3 * HDIM + j] + bhh[3 * HDIM + j];
        float cv = sigm(gf) * g_c[b * HDIM + j] + sigm(gi) * tanhf(gg);
        float hv = sigm(go) * tanhf(cv);
        g_c[b * HDIM + j] = cv;
        g_hn[b * HDIM + j] = hv;
    }
}

// ---------------- output projection: reads g_hn; writes dst + g_inp; advances g_h ----------------
__global__ __launch_bounds__(256) void k_outproj(
    const float* __restrict__ outW, const float* __restrict__ outb,
    float* __restrict__ dst) {
    // state advance (race-free: everyone else only reads g_hn)
    if (blockIdx.x < 32) {
        int i = blockIdx.x * 256 + threadIdx.x;
        if (i < BDIM * HDIM) g_h[i] = g_hn[i];
    }
    __shared__ float hsm[BDIM][HDIM];
    int tid = threadIdx.x;
    for (int i = tid; i < BDIM * HDIM; i += 256) hsm[i / HDIM][i % HDIM] = g_hn[i];
    __syncthreads();
    int w = tid >> 5, lane = tid & 31;
#pragma unroll
    for (int rr = 0; rr < 4; rr++) {
        int e = blockIdx.x * 32 + w * 4 + rr;
        if (e >= EDIM) break;
        const float* wr = outW + (size_t)e * HDIM;
        float acc[8];
#pragma unroll
        for (int b = 0; b < 8; b++) acc[b] = 0.f;
        for (int k = lane * 4; k < HDIM; k += 128) {
            float4 wv = *(const float4*)(wr + k);
#pragma unroll
            for (int b = 0; b < 8; b++) {
                float4 h4 = *(const float4*)&hsm[b][k];
                acc[b] += wv.x * h4.x + wv.y * h4.y + wv.z * h4.z + wv.w * h4.w;
            }
        }
#pragma unroll
        for (int b = 0; b < 8; b++) acc[b] = wredsum(acc[b]);
        if (lane < 8) {
            float v = acc[lane] + outb[e];
            dst[(size_t)lane * EDIM + e] = v;
            g_inp[(size_t)lane * EDIM + e] = v;
        }
    }
}

// ---------------- host ----------------
extern "C" void kernel_launch(void* const* d_in, const int* in_sizes, int n_in,
                              void* d_out, int out_size) {
    // Expected element counts in metadata order (target_size scalar auto-skipped).
    static const long long EXP[20] = {
        (long long)BDIM * TDIM * EDIM,        // input
        64LL * BDIM * NZDIM,                  // noise1
        64LL * BDIM * HDIM,                   // noise2
        (long long)BDIM * EDIM,               // init_dec_input
        (long long)GDIM * EDIM,               // enc_Wih
        (long long)GDIM * HDIM,               // enc_Whh
        GDIM, GDIM,                           // enc_bih, enc_bhh
        (long long)GDIM * HDIM,               // dec_Wih
        (long long)GDIM * HDIM,               // dec_Whh
        GDIM, GDIM,                           // dec_bih, dec_bhh
        (long long)HDIM * (EDIM + NZDIM),     // emb_W
        HDIM,                                 // emb_b
        (long long)TDIM * 3 * HDIM,           // attn_W
        TDIM,                                 // attn_b
        (long long)HDIM * 2 * HDIM,           // comb_W
        HDIM,                                 // comb_b
        (long long)EDIM * HDIM,               // out_W
        EDIM                                  // out_b
    };
    const float* P[20];
    bool ok = true;
    {
        int idx = 0;
        for (int e = 0; e < 20; e++) {
            int j = idx;
            while (j < n_in && (long long)in_sizes[j] != EXP[e]) j++;
            if (j >= n_in) { ok = false; break; }
            P[e] = (const float*)d_in[j];
            idx = j + 1;
        }
    }
    if (!ok) {  // positional fallback (skip target_size slot if present)
        int idx = 0;
        for (int e = 0; e < 20; e++) {
            if (e == 1 && n_in >= 21) idx++;
            P[e] = (const float*)d_in[idx++];
        }
    }
    const float* input    = P[0];
    const float* noise1   = P[1];
    const float* noise2   = P[2];
    const float* init_dec = P[3];
    const float* enc_Wih  = P[4];
    const float* enc_Whh  = P[5];
    const float* enc_bih  = P[6];
    const float* enc_bhh  = P[7];
    const float* dec_Wih  = P[8];
    const float* dec_Whh  = P[9];
    const float* dec_bih  = P[10];
    const float* dec_bhh  = P[11];
    const float* emb_W    = P[12];
    const float* emb_b    = P[13];
    const float* attn_W   = P[14];
    const float* attn_b   = P[15];
    const float* comb_W   = P[16];
    const float* comb_b   = P[17];
    const float* out_W    = P[18];
    const float* out_b    = P[19];
    float* out = (float*)d_out;

    int S = out_size / (BDIM * EDIM);

    k_init<<<32, 256>>>();

    dim3 gproj((GDIM + 127) / 128, MDIM / 128);
    k_enc_proj<<<gproj, 256>>>(input, enc_Wih, enc_bih, enc_bhh);

    for (int t = 0; t < TDIM; t++)
        k_enc_step<<<125, 256>>>(enc_Whh, t);

    k_prepdec<<<(BDIM * EDIM + 255) / 256, 256>>>(init_dec);

    for (int s = 0; s < S; s++) {
        k_cgemm<<<125, 256>>>(noise1 + (size_t)s * BDIM * NZDIM, emb_W, emb_b, 0);
        k_attn<<<BDIM, 256>>>(attn_W, attn_b, noise2 + (size_t)s * BDIM * HDIM);
        k_applied<<<32, 256>>>();
        k_cgemm<<<125, 256>>>((const float*)0, comb_W, comb_b, 1);
        k_declstm<<<125, 256>>>(dec_Wih, dec_Whh, dec_bih, dec_bhh);
        k_outproj<<<(EDIM + 31) / 32, 256>>>(out_W, out_b, out + (size_t)s * BDIM * EDIM);
    }
}

// round 5
// speedup vs baseline: 3.1859x; 3.1859x over previous
#include <cuda_runtime.h>
#include <math.h>

#define BDIM 8
#define TDIM 128
#define EDIM 30522
#define HDIM 1000
#define NZDIM 10000
#define GDIM 4000   // 4*H
#define MDIM 1024   // T*B
#define SMAX 64

// ---------------- scratch (device globals; referenced ONLY from device code) ----------------
__device__ float g_Xg[(size_t)MDIM * GDIM];          // encoder input projection [T*B, 4H]
__device__ float g_enc[(size_t)TDIM * BDIM * HDIM];  // encoder outputs [T, B, H]
__device__ float g_hbuf[2][BDIM * HDIM];             // encoder double-buffered hidden
__device__ float g_c[BDIM * HDIM];                   // cell state
__device__ float g_hd[2][BDIM * HDIM];               // decoder hidden ping-pong
__device__ float g_hall[(size_t)SMAX * BDIM * HDIM]; // all decoder hiddens
__device__ float g_emb[BDIM * HDIM];
__device__ float g_aw[BDIM * TDIM];
__device__ float g_app[BDIM * HDIM];
__device__ float g_outc[BDIM * HDIM];
__device__ float g_M[(size_t)HDIM * HDIM];           // emb_WE @ out_W
__device__ float g_npre[(size_t)SMAX * BDIM * HDIM]; // noise1@emb_Wnz^T + emb_b
__device__ float g_emb0[BDIM * HDIM];                // init_dec @ emb_WE^T
__device__ float g_vvec[HDIM];                       // emb_WE @ out_b
__device__ float g_i9[9 * EDIM];                     // [init_dec rows 0..7 | out_b]
__device__ float g_part[4000000];                    // K-split partials
__device__ unsigned g_bcnt = 0, g_bgen = 0;          // grid barrier

__device__ __forceinline__ float sigm(float x) { return 1.f / (1.f + __expf(-x)); }

__device__ __forceinline__ float wredsum(float v) {
#pragma unroll
    for (int o = 16; o; o >>= 1) v += __shfl_xor_sync(0xffffffffu, v, o);
    return v;
}

// ---------------- init ----------------
__global__ __launch_bounds__(256) void k_init() {
    int i = blockIdx.x * 256 + threadIdx.x;
    if (i < BDIM * HDIM) { g_hbuf[0][i] = 0.f; g_c[i] = 0.f; }
}

// ---------------- generic tiled SGEMM: C[M,N] = A[M,K] * op(B) (+bias) ----------------
// bt=1: B is [N,K] row-major (NT, k-contiguous rows, +boff col offset)
// bt=0: B is [K,N] row-major (NN)
// aperm=1: A row m maps to physical row (m&7)*TDIM + (m>>3)   (encoder input permute)
// asel: 0=Aext 1=g_hall 2=g_i9 ; zsplit>1 -> write partials to g_part[z]
__global__ __launch_bounds__(256) void k_gemm(
    const float* __restrict__ Aext, int asel, int aperm,
    int M, int N, int K, int lda,
    const float* __restrict__ B, int ldb, int boff, int bt,
    float* __restrict__ Cext, int csel, int ldc,
    const float* __restrict__ bias0, const float* __restrict__ bias1,
    int zsplit)
{
    __shared__ __align__(16) float As[2][16][128];
    __shared__ __align__(16) float Bs[2][16][128];

    const float* A = Aext;
    if (asel == 1) A = g_hall;
    else if (asel == 2) A = g_i9;

    int z = blockIdx.z;
    int kchunk = (((K + zsplit - 1) / zsplit) + 15) & ~15;
    int kbeg = z * kchunk;
    int kend = min(K, kbeg + kchunk);

    int bm = blockIdx.y * 128, bn = blockIdx.x * 128;
    int tid = threadIdx.x;
    int tx = tid & 15, ty = tid >> 4;
    int lr = tid >> 1;            // 0..127
    int lk = (tid & 1) * 8;       // 0 or 8
    int nk = tid >> 4;            // 0..15 (NN)
    int nn = (tid & 15) * 8;      // NN col

    float2 pa[4], pb2[4];
    float4 pb4[2];

    auto loadA = [&](int k0) {
        int m = bm + lr;
        bool rowok = (m < M);
        size_t grow = aperm ? ((size_t)(m & 7) * TDIM + (m >> 3)) : (size_t)m;
        const float* src = A + grow * lda + (k0 + lk);
        int krem = kend - (k0 + lk);
        if (rowok && krem >= 8) {
            pa[0] = *(const float2*)(src);
            pa[1] = *(const float2*)(src + 2);
            pa[2] = *(const float2*)(src + 4);
            pa[3] = *(const float2*)(src + 6);
        } else {
            float t[8];
#pragma unroll
            for (int c = 0; c < 8; c++) t[c] = (rowok && c < krem) ? src[c] : 0.f;
            pa[0] = make_float2(t[0], t[1]); pa[1] = make_float2(t[2], t[3]);
            pa[2] = make_float2(t[4], t[5]); pa[3] = make_float2(t[6], t[7]);
        }
    };
    auto storeA = [&](int buf) {
        As[buf][lk + 0][lr] = pa[0].x; As[buf][lk + 1][lr] = pa[0].y;
        As[buf][lk + 2][lr] = pa[1].x; As[buf][lk + 3][lr] = pa[1].y;
        As[buf][lk + 4][lr] = pa[2].x; As[buf][lk + 5][lr] = pa[2].y;
        As[buf][lk + 6][lr] = pa[3].x; As[buf][lk + 7][lr] = pa[3].y;
    };
    auto loadB = [&](int k0) {
        if (bt) {
            int n = bn + lr;
            bool rowok = (n < N);
            const float* src = B + (size_t)n * ldb + boff + (k0 + lk);
            int krem = kend - (k0 + lk);
            if (rowok && krem >= 8) {
                pb2[0] = *(const float2*)(src);
                pb2[1] = *(const float2*)(src + 2);
                pb2[2] = *(const float2*)(src + 4);
                pb2[3] = *(const float2*)(src + 6);
            } else {
                float t[8];
#pragma unroll
                for (int c = 0; c < 8; c++) t[c] = (rowok && c < krem) ? src[c] : 0.f;
                pb2[0] = make_float2(t[0], t[1]); pb2[1] = make_float2(t[2], t[3]);
                pb2[2] = make_float2(t[4], t[5]); pb2[3] = make_float2(t[6], t[7]);
            }
        } else {
            int kk = k0 + nk;
            bool kok = (kk < kend);
            const float* src = B + (size_t)kk * ldb + bn + nn;
            if (kok && bn + nn + 8 <= N) {
                pb4[0] = *(const float4*)(src);
                pb4[1] = *(const float4*)(src + 4);
            } else {
                float t[8];
#pragma unroll
                for (int c = 0; c < 8; c++) t[c] = (kok && bn + nn + c < N) ? src[c] : 0.f;
                pb4[0] = make_float4(t[0], t[1], t[2], t[3]);
                pb4[1] = make_float4(t[4], t[5], t[6], t[7]);
            }
        }
    };
    auto storeB = [&](int buf) {
        if (bt) {
            Bs[buf][lk + 0][lr] = pb2[0].x; Bs[buf][lk + 1][lr] = pb2[0].y;
            Bs[buf][lk + 2][lr] = pb2[1].x; Bs[buf][lk + 3][lr] = pb2[1].y;
            Bs[buf][lk + 4][lr] = pb2[2].x; Bs[buf][lk + 5][lr] = pb2[2].y;
            Bs[buf][lk + 6][lr] = pb2[3].x; Bs[buf][lk + 7][lr] = pb2[3].y;
        } else {
            *(float4*)&Bs[buf][nk][nn] = pb4[0];
            *(float4*)&Bs[buf][nk][nn + 4] = pb4[1];
        }
    };

    float acc[8][8];
#pragma unroll
    for (int i = 0; i < 8; i++)
#pragma unroll
        for (int j = 0; j < 8; j++) acc[i][j] = 0.f;

    int ntiles = (kend > kbeg) ? ((kend - kbeg + 15) >> 4) : 0;
    if (ntiles > 0) {
        loadA(kbeg); loadB(kbeg);
        storeA(0); storeB(0);
        __syncthreads();
        for (int it = 0; it < ntiles; it++) {
            int buf = it & 1;
            if (it + 1 < ntiles) { loadA(kbeg + (it + 1) * 16); loadB(kbeg + (it + 1) * 16); }
#pragma unroll
            for (int kk = 0; kk < 16; kk++) {
                float a[8], b[8];
                *(float4*)&a[0] = *(const float4*)&As[buf][kk][ty * 4];
                *(float4*)&a[4] = *(const float4*)&As[buf][kk][64 + ty * 4];
                *(float4*)&b[0] = *(const float4*)&Bs[buf][kk][tx * 4];
                *(float4*)&b[4] = *(const float4*)&Bs[buf][kk][64 + tx * 4];
#pragma unroll
                for (int i = 0; i < 8; i++)
#pragma unroll
                    for (int j = 0; j < 8; j++) acc[i][j] += a[i] * b[j];
            }
            if (it + 1 < ntiles) {
                storeA(buf ^ 1); storeB(buf ^ 1);
            }
            __syncthreads();
        }
    }

    if (zsplit > 1) {
        float* Cp = g_part + (size_t)z * M * N;
#pragma unroll
        for (int i = 0; i < 8; i++) {
            int m = bm + ((i < 4) ? ty * 4 + i : 64 + ty * 4 + (i - 4));
            if (m >= M) continue;
#pragma unroll
            for (int j = 0; j < 8; j++) {
                int n = bn + ((j < 4) ? tx * 4 + j : 64 + tx * 4 + (j - 4));
                if (n < N) Cp[(size_t)m * N + n] = acc[i][j];
            }
        }
    } else {
        float* Cp = (csel == 1) ? g_Xg : Cext;
#pragma unroll
        for (int i = 0; i < 8; i++) {
            int m = bm + ((i < 4) ? ty * 4 + i : 64 + ty * 4 + (i - 4));
            if (m >= M) continue;
#pragma unroll
            for (int j = 0; j < 8; j++) {
                int n = bn + ((j < 4) ? tx * 4 + j : 64 + tx * 4 + (j - 4));
                if (n < N) {
                    float v = acc[i][j];
                    if (bias0) v += bias0[n];
                    if (bias1) v += bias1[n];
                    Cp[(size_t)m * ldc + n] = v;
                }
            }
        }
    }
}

// ---------------- reduce K-split partials ----------------
// dsel: 0 -> g_M, 1 -> g_npre, 2 -> g_emb0 (m<8) + g_vvec (m==8)
__global__ __launch_bounds__(256) void k_reduce(int zs, int Mr, int Nr, int dsel,
                                                const float* __restrict__ bias) {
    int idx = blockIdx.x * 256 + threadIdx.x;
    int total = Mr * Nr;
    if (idx >= total) return;
    int n = idx % Nr;
    float s = 0.f;
    for (int z = 0; z < zs; z++) s += g_part[(size_t)z * total + idx];
    if (bias) s += bias[n];
    if (dsel == 0) g_M[idx] = s;
    else if (dsel == 1) g_npre[idx] = s;
    else {
        int m = idx / Nr;
        if (m < 8) g_emb0[idx] = s;
        else g_vvec[n] = s;
    }
}

// ---------------- grid barrier ----------------
__device__ __forceinline__ void gbar(unsigned gen0, unsigned step, unsigned nb) {
    __threadfence();
    __syncthreads();
    if (threadIdx.x == 0) {
        unsigned old = atomicAdd(&g_bcnt, 1);
        if (old == nb - 1) {
            atomicExch(&g_bcnt, 0);
            atomicAdd(&g_bgen, 1);
        } else {
            while (atomicAdd(&g_bgen, 0) - gen0 < step) __nanosleep(64);
        }
        __threadfence();
    }
    __syncthreads();
}

// ---------------- persistent encoder: 128 LSTM steps in one kernel ----------------
__global__ __launch_bounds__(256) void k_enc_persist(const float* __restrict__ Whh) {
    __shared__ float hs[BDIM][HDIM];
    unsigned gen0 = 0;
    if (threadIdx.x == 0) gen0 = atomicAdd(&g_bgen, 0);
    int tid = threadIdx.x, w = tid >> 5, lane = tid & 31;
    int j = blockIdx.x * 8 + w;
    const float* w0 = Whh + (size_t)j * HDIM;
    const float* w1 = Whh + (size_t)(HDIM + j) * HDIM;
    const float* w2 = Whh + (size_t)(2 * HDIM + j) * HDIM;
    const float* w3 = Whh + (size_t)(3 * HDIM + j) * HDIM;

    for (int t = 0; t < TDIM; t++) {
        const float* hin = g_hbuf[t & 1];
        float* hout = g_hbuf[(t & 1) ^ 1];
        for (int i = tid; i < BDIM * HDIM; i += 256) hs[i / HDIM][i % HDIM] = hin[i];
        __syncthreads();
        float acc[4][8];
#pragma unroll
        for (int g = 0; g < 4; g++)
#pragma unroll
            for (int b = 0; b < 8; b++) acc[g][b] = 0.f;
        for (int k = lane * 4; k < HDIM; k += 128) {
            float4 v0 = *(const float4*)(w0 + k);
            float4 v1 = *(const float4*)(w1 + k);
            float4 v2 = *(const float4*)(w2 + k);
            float4 v3 = *(const float4*)(w3 + k);
#pragma unroll
            for (int b = 0; b < 8; b++) {
                float4 h4 = *(const float4*)&hs[b][k];
                acc[0][b] += v0.x * h4.x + v0.y * h4.y + v0.z * h4.z + v0.w * h4.w;
                acc[1][b] += v1.x * h4.x + v1.y * h4.y + v1.z * h4.z + v1.w * h4.w;
                acc[2][b] += v2.x * h4.x + v2.y * h4.y + v2.z * h4.z + v2.w * h4.w;
                acc[3][b] += v3.x * h4.x + v3.y * h4.y + v3.z * h4.z + v3.w * h4.w;
            }
        }
#pragma unroll
        for (int g = 0; g < 4; g++)
#pragma unroll
            for (int b = 0; b < 8; b++) acc[g][b] = wredsum(acc[g][b]);
        if (lane < 8) {
            int b = lane;
            const float* xr = g_Xg + ((size_t)t * BDIM + b) * GDIM;
            float gi = xr[j] + acc[0][b];
            float gf = xr[HDIM + j] + acc[1][b];
            float gg = xr[2 * HDIM + j] + acc[2][b];
            float go = xr[3 * HDIM + j] + acc[3][b];
            float cv = sigm(gf) * g_c[b * HDIM + j] + sigm(gi) * tanhf(gg);
            float hv = sigm(go) * tanhf(cv);
            g_c[b * HDIM + j] = cv;
            hout[b * HDIM + j] = hv;
            g_enc[((size_t)t * BDIM + b) * HDIM + j] = hv;
            if (t == TDIM - 1) g_hd[0][b * HDIM + j] = hv;
        }
        gbar(gen0, (unsigned)(t + 1), gridDim.x);
    }
}

// ---------------- i9 staging: rows 0..7 = init_dec, row 8 = out_b ----------------
__global__ __launch_bounds__(256) void k_copy_i9(const float* __restrict__ init_dec,
                                                 const float* __restrict__ outb) {
    int i = blockIdx.x * 256 + threadIdx.x;
    if (i < 8 * EDIM) g_i9[i] = init_dec[i];
    else if (i < 9 * EDIM) g_i9[i] = outb[i - 8 * EDIM];
}

// ---------------- per-step emb: emb = (s? h@M^T + v : emb0) + npre[s] ----------------
__global__ __launch_bounds__(256) void k_emb(int s) {
    int p = s & 1;
    int tid = threadIdx.x, w = tid >> 5, lane = tid & 31;
    int j = blockIdx.x * 8 + w;
    if (s == 0) {
        if (lane < 8) {
            int b = lane;
            g_emb[b * HDIM + j] = g_emb0[b * HDIM + j] + g_npre[b * HDIM + j];
        }
        return;
    }
    __shared__ float hs[BDIM][HDIM];
    const float* hin = g_hd[p];
    for (int i = tid; i < BDIM * HDIM; i += 256) hs[i / HDIM][i % HDIM] = hin[i];
    __syncthreads();
    const float* mr = g_M + (size_t)j * HDIM;
    float acc[8];
#pragma unroll
    for (int b = 0; b < 8; b++) acc[b] = 0.f;
    for (int k = lane * 4; k < HDIM; k += 128) {
        float4 mv = *(const float4*)(mr + k);
#pragma unroll
        for (int b = 0; b < 8; b++) {
            float4 h4 = *(const float4*)&hs[b][k];
            acc[b] += mv.x * h4.x + mv.y * h4.y + mv.z * h4.z + mv.w * h4.w;
        }
    }
#pragma unroll
    for (int b = 0; b < 8; b++) acc[b] = wredsum(acc[b]);
    if (lane < 8) {
        int b = lane;
        g_emb[b * HDIM + j] = acc[b] + g_vvec[j] + g_npre[((size_t)s * 8 + b) * HDIM + j];
    }
}

// ---------------- attention scores + softmax ----------------
__global__ __launch_bounds__(256) void k_attn(
    const float* __restrict__ attW, const float* __restrict__ attb,
    const float* __restrict__ n2, int s) {
    int p = s & 1;
    int b = blockIdx.x;
    __shared__ float xs[3 * HDIM];
    __shared__ float sc[TDIM];
    int tid = threadIdx.x;
    for (int i = tid; i < HDIM; i += 256) {
        xs[i] = g_emb[b * HDIM + i];
        xs[HDIM + i] = g_hd[p][b * HDIM + i];
        xs[2 * HDIM + i] = n2[b * HDIM + i];
    }
    __syncthreads();
    int w = tid >> 5, lane = tid & 31;
    for (int t = w; t < TDIM; t += 8) {
        const float* wr = attW + (size_t)t * 3 * HDIM;
        float a = 0.f;
        for (int k = lane * 4; k < 3 * HDIM; k += 128) {
            float4 wv = *(const float4*)(wr + k);
            float4 xv = *(const float4*)&xs[k];
            a += wv.x * xv.x + wv.y * xv.y + wv.z * xv.z + wv.w * xv.w;
        }
        a = wredsum(a);
        if (lane == 0) sc[t] = a + attb[t];
    }
    __syncthreads();
    if (w == 0) {
        float4 v = *(const float4*)&sc[lane * 4];
        float m = fmaxf(fmaxf(v.x, v.y), fmaxf(v.z, v.w));
#pragma unroll
        for (int o = 16; o; o >>= 1) m = fmaxf(m, __shfl_xor_sync(0xffffffffu, m, o));
        float e0 = __expf(v.x - m), e1 = __expf(v.y - m);
        float e2 = __expf(v.z - m), e3 = __expf(v.w - m);
        float ssum = wredsum(e0 + e1 + e2 + e3);
        float inv = 1.f / ssum;
        float4 r = make_float4(e0 * inv, e1 * inv, e2 * inv, e3 * inv);
        *(float4*)&g_aw[b * TDIM + lane * 4] = r;
    }
}

// ---------------- applied = aw @ enc ----------------
__global__ __launch_bounds__(256) void k_applied() {
    int b = blockIdx.x >> 2;
    int h0 = (blockIdx.x & 3) * 250;
    __shared__ float aws[TDIM];
    if (threadIdx.x < TDIM) aws[threadIdx.x] = g_aw[b * TDIM + threadIdx.x];
    __syncthreads();
    if (threadIdx.x < 250) {
        int h = h0 + threadIdx.x;
        float a = 0.f;
#pragma unroll 8
        for (int t = 0; t < TDIM; t++)
            a += aws[t] * g_enc[((size_t)t * BDIM + b) * HDIM + h];
        g_app[b * HDIM + h] = a;
    }
}

// ---------------- comb: out = relu([emb|app] @ comb_W^T + comb_b) ----------------
#define KC 1024
__global__ __launch_bounds__(256) void k_comb(
    const float* __restrict__ W, const float* __restrict__ bias) {
    __shared__ float xs[BDIM][KC];
    const int K = 2 * HDIM;
    int tid = threadIdx.x, w = tid >> 5, lane = tid & 31;
    int j = blockIdx.x * 8 + w;
    const float* wr = W + (size_t)j * K;
    float acc[8];
#pragma unroll
    for (int b = 0; b < 8; b++) acc[b] = 0.f;

    for (int k0 = 0; k0 < K; k0 += KC) {
        int kc = min(KC, K - k0);
        int kcp = (kc + 3) & ~3;
        __syncthreads();
        for (int i = tid; i < BDIM * kcp; i += 256) {
            int b = i / kcp, kk = i - b * kcp;
            int k = k0 + kk;
            float v = 0.f;
            if (kk < kc) v = (k < HDIM) ? g_emb[(size_t)b * HDIM + k]
                                        : g_app[(size_t)b * HDIM + (k - HDIM)];
            xs[b][kk] = v;
        }
        __syncthreads();
#pragma unroll 4
        for (int kk = lane * 2; kk < kc; kk += 64) {
            int k = k0 + kk;
            float2 wv;
            if (kk + 2 <= kc) wv = *(const float2*)(wr + k);
            else { wv.x = wr[k]; wv.y = 0.f; }
#pragma unroll
            for (int b = 0; b < 8; b++) {
                float2 xv = *(const float2*)&xs[b][kk];
                acc[b] += wv.x * xv.x;
                acc[b] += wv.y * xv.y;
            }
        }
    }
#pragma unroll
    for (int b = 0; b < 8; b++) acc[b] = wredsum(acc[b]);
    if (lane < 8) {
        float v = acc[lane] + bias[j];
        g_outc[lane * HDIM + j] = fmaxf(v, 0.f);
    }
}

// ---------------- decoder LSTM ----------------
__global__ __launch_bounds__(256) void k_declstm(
    const float* __restrict__ Wih, const float* __restrict__ Whh,
    const float* __restrict__ bih, const float* __restrict__ bhh, int s) {
    int p = s & 1;
    __shared__ float xs[BDIM][HDIM];
    int tid = threadIdx.x, w = tid >> 5, lane = tid & 31;
    int j = blockIdx.x * 8 + w;
    float acc[4][8];
#pragma unroll
    for (int g = 0; g < 4; g++)
#pragma unroll
        for (int b = 0; b < 8; b++) acc[g][b] = 0.f;

    for (int src = 0; src < 2; src++) {
        const float* sp = src ? (const float*)g_hd[p] : (const float*)g_outc;
        const float* Wm = src ? Whh : Wih;
        __syncthreads();
        for (int i = tid; i < BDIM * HDIM; i += 256) xs[i / HDIM][i % HDIM] = sp[i];
        __syncthreads();
        const float* w0 = Wm + (size_t)j * HDIM;
        const float* w1 = Wm + (size_t)(HDIM + j) * HDIM;
        const float* w2 = Wm + (size_t)(2 * HDIM + j) * HDIM;
        const float* w3 = Wm + (size_t)(3 * HDIM + j) * HDIM;
        for (int k = lane * 4; k < HDIM; k += 128) {
            float4 v0 = *(const float4*)(w0 + k);
            float4 v1 = *(const float4*)(w1 + k);
            float4 v2 = *(const float4*)(w2 + k);
            float4 v3 = *(const float4*)(w3 + k);
#pragma unroll
            for (int b = 0; b < 8; b++) {
                float4 h4 = *(const float4*)&xs[b][k];
                acc[0][b] += v0.x * h4.x + v0.y * h4.y + v0.z * h4.z + v0.w * h4.w;
                acc[1][b] += v1.x * h4.x + v1.y * h4.y + v1.z * h4.z + v1.w * h4.w;
                acc[2][b] += v2.x * h4.x + v2.y * h4.y + v2.z * h4.z + v2.w * h4.w;
                acc[3][b] += v3.x * h4.x + v3.y * h4.y + v3.z * h4.z + v3.w * h4.w;
            }
        }
    }
#pragma unroll
    for (int g = 0; g < 4; g++)
#pragma unroll
        for (int b = 0; b < 8; b++) acc[g][b] = wredsum(acc[g][b]);
    if (lane < 8) {
        int b = lane;
        float gi = acc[0][b] + bih[j] + bhh[j];
        float gf = acc[1][b] + bih[HDIM + j] + bhh[HDIM + j];
        float gg = acc[2][b] + bih[2 * HDIM + j] + bhh[2 * HDIM + j];
        float go = acc[3][b] + bih[3 * HDIM + j] + bhh[3 * HDIM + j];
        float cv = sigm(gf) * g_c[b * HDIM + j] + sigm(gi) * tanhf(gg);
        float hv = sigm(go) * tanhf(cv);
        g_c[b * HDIM + j] = cv;
        g_hd[p ^ 1][b * HDIM + j] = hv;
        g_hall[((size_t)s * 8 + b) * HDIM + j] = hv;
    }
}

// ---------------- host ----------------
extern "C" void kernel_launch(void* const* d_in, const int* in_sizes, int n_in,
                              void* d_out, int out_size) {
    static const long long EXP[20] = {
        (long long)BDIM * TDIM * EDIM, 64LL * BDIM * NZDIM, 64LL * BDIM * HDIM,
        (long long)BDIM * EDIM,
        (long long)GDIM * EDIM, (long long)GDIM * HDIM, GDIM, GDIM,
        (long long)GDIM * HDIM, (long long)GDIM * HDIM, GDIM, GDIM,
        (long long)HDIM * (EDIM + NZDIM), HDIM,
        (long long)TDIM * 3 * HDIM, TDIM,
        (long long)HDIM * 2 * HDIM, HDIM,
        (long long)EDIM * HDIM, EDIM
    };
    const float* P[20];
    bool ok = true;
    {
        int idx = 0;
        for (int e = 0; e < 20; e++) {
            int j = idx;
            while (j < n_in && (long long)in_sizes[j] != EXP[e]) j++;
            if (j >= n_in) { ok = false; break; }
            P[e] = (const float*)d_in[j];
            idx = j + 1;
        }
    }
    if (!ok) {
        int idx = 0;
        for (int e = 0; e < 20; e++) {
            if (e == 1 && n_in >= 21) idx++;
            P[e] = (const float*)d_in[idx++];
        }
    }
    const float* input    = P[0];
    const float* noise1   = P[1];
    const float* noise2   = P[2];
    const float* init_dec = P[3];
    const float* enc_Wih  = P[4];
    const float* enc_Whh  = P[5];
    const float* enc_bih  = P[6];
    const float* enc_bhh  = P[7];
    const float* dec_Wih  = P[8];
    const float* dec_Whh  = P[9];
    const float* dec_bih  = P[10];
    const float* dec_bhh  = P[11];
    const float* emb_W    = P[12];
    const float* emb_b    = P[13];
    const float* attn_W   = P[14];
    const float* attn_b   = P[15];
    const float* comb_W   = P[16];
    const float* comb_b   = P[17];
    const float* out_W    = P[18];
    const float* out_b    = P[19];
    float* out = (float*)d_out;

    int S = out_size / (BDIM * EDIM);
    if (S > SMAX) S = SMAX;
    int Mn = S * 8;

    k_init<<<32, 256>>>();

    // encoder input projection: [1024, 4000] = input(perm) @ enc_Wih^T + biases
    {
        dim3 g((GDIM + 127) / 128, (MDIM + 127) / 128, 1);
        k_gemm<<<g, 256>>>(input, 0, 1, MDIM, GDIM, EDIM, EDIM,
                           enc_Wih, EDIM, 0, 1,
                           nullptr, 1, GDIM, enc_bih, enc_bhh, 1);
    }
    k_enc_persist<<<125, 256>>>(enc_Whh);

    // precomputes
    k_copy_i9<<<(9 * EDIM + 255) / 256, 256>>>(init_dec, out_b);
    {   // M = emb_WE @ out_W  (NN, K-split 4)
        dim3 g(8, 8, 4);
        k_gemm<<<g, 256>>>(emb_W, 0, 0, HDIM, HDIM, EDIM, EDIM + NZDIM,
                           out_W, HDIM, 0, 0,
                           nullptr, 0, 0, nullptr, nullptr, 4);
        k_reduce<<<(HDIM * HDIM + 255) / 256, 256>>>(4, HDIM, HDIM, 0, nullptr);
    }
    {   // npre = noise1 @ emb_Wnz^T + emb_b  (NT, K-split 4)
        dim3 g(8, (Mn + 127) / 128, 4);
        k_gemm<<<g, 256>>>(noise1, 0, 0, Mn, HDIM, NZDIM, NZDIM,
                           emb_W, EDIM + NZDIM, EDIM, 1,
                           nullptr, 0, 0, nullptr, nullptr, 4);
        k_reduce<<<(Mn * HDIM + 255) / 256, 256>>>(4, Mn, HDIM, 1, emb_b);
    }
    {   // [emb0 | v] = i9 @ emb_WE^T  (NT, K-split 16)
        dim3 g(8, 1, 16);
        k_gemm<<<g, 256>>>(nullptr, 2, 0, 9, HDIM, EDIM, EDIM,
                           emb_W, EDIM + NZDIM, 0, 1,
                           nullptr, 0, 0, nullptr, nullptr, 16);
        k_reduce<<<(9 * HDIM + 255) / 256, 256>>>(16, 9, HDIM, 2, nullptr);
    }

    // decoder loop (no E-dim work inside)
    for (int s = 0; s < S; s++) {
        k_emb<<<125, 256>>>(s);
        k_attn<<<BDIM, 256>>>(attn_W, attn_b, noise2 + (size_t)s * BDIM * HDIM, s);
        k_applied<<<32, 256>>>();
        k_comb<<<125, 256>>>(comb_W, comb_b);
        k_declstm<<<125, 256>>>(dec_Wih, dec_Whh, dec_bih, dec_bhh, s);
    }

    // final: out[512, 30522] = g_hall @ out_W^T + out_b
    {
        dim3 g((EDIM + 127) / 128, (Mn + 127) / 128, 1);
        k_gemm<<<g, 256>>>(nullptr, 1, 0, Mn, EDIM, HDIM, HDIM,
                           out_W, HDIM, 0, 1,
                           out, 0, EDIM, out_b, nullptr, 1);
    }
}